// round 2
// baseline (speedup 1.0000x reference)
#include <cuda_runtime.h>
#include <cstdint>

// ----------------------------------------------------------------------------
// WindowAttention: 2048 windows x 8 heads, M=N=64, D=64, fp32.
// Per CTA: one (b,h). 128 threads, 4 warps; warp w owns query rows [16w,16w+16).
// S = (Q*scale) K^T + bias ; P = softmax_m(S) ; O = P V ; rolled writeback.
// tf32 mma.sync with 3-term split for QK and V-split for PV (near-fp32 logits).
// ----------------------------------------------------------------------------

#define STRIDE 68          // smem row stride in floats (bank-conflict-free A/B loads)
#define SM_TILE (64 * STRIDE)

__device__ float g_bias[8 * 64 * 64];   // precomputed bias[h][n][m]

__global__ void bias_precompute_kernel(const float* __restrict__ table) {
    int t = blockIdx.x * blockDim.x + threadIdx.x;   // 0..4095 = n*64+m
    if (t >= 4096) return;
    int n = t >> 6, m = t & 63;
    int raw = (n - 32) * 128 + (m - 32) + 64;        // range [-4064, 4063]
    int idx = raw < 0 ? raw + 16129 : raw;           // python-style mod
    const float* row = table + (size_t)idx * 8;
#pragma unroll
    for (int h = 0; h < 8; ++h)
        g_bias[h * 4096 + t] = row[h];
}

__device__ __forceinline__ uint32_t f2tf32(float x) {
    uint32_t r;
    asm("cvt.rna.tf32.f32 %0, %1;" : "=r"(r) : "f"(x));
    return r;
}

__device__ __forceinline__ void split_tf32(float x, uint32_t& hi, uint32_t& lo) {
    hi = f2tf32(x);
    lo = f2tf32(x - __uint_as_float(hi));
}

__device__ __forceinline__ void mma_tf32(float c[4],
                                         uint32_t a0, uint32_t a1, uint32_t a2, uint32_t a3,
                                         uint32_t b0, uint32_t b1) {
    asm volatile(
        "mma.sync.aligned.m16n8k8.row.col.f32.tf32.tf32.f32 "
        "{%0,%1,%2,%3}, {%4,%5,%6,%7}, {%8,%9}, {%0,%1,%2,%3};"
        : "+f"(c[0]), "+f"(c[1]), "+f"(c[2]), "+f"(c[3])
        : "r"(a0), "r"(a1), "r"(a2), "r"(a3), "r"(b0), "r"(b1));
}

__global__ __launch_bounds__(128) void winattn_kernel(
    const float* __restrict__ q, const float* __restrict__ k,
    const float* __restrict__ v, float* __restrict__ out) {
    extern __shared__ float smem[];
    float* sQ = smem;                 // also reused as P buffer
    float* sK = smem + SM_TILE;
    float* sV = smem + 2 * SM_TILE;

    const int bh   = blockIdx.x;
    const int b    = bh >> 3;
    const int h    = bh & 7;
    const int tid  = threadIdx.x;
    const int lane = tid & 31;
    const int g    = lane >> 2;       // group id (0..7)
    const int tig  = lane & 3;        // thread in group (0..3)
    const int r0   = (tid >> 5) * 16; // warp's first query row

    // ---- load Q (pre-scaled), K, V into padded smem -------------------------
    {
        const float4* qg = (const float4*)(q + (size_t)bh * 4096);
        const float4* kg = (const float4*)(k + (size_t)bh * 4096);
        const float4* vg = (const float4*)(v + (size_t)bh * 4096);
#pragma unroll
        for (int i = tid; i < 1024; i += 128) {
            int m = i >> 4, c4 = i & 15;
            float4 qv = qg[i];
            qv.x *= 0.125f; qv.y *= 0.125f; qv.z *= 0.125f; qv.w *= 0.125f;
            *(float4*)(sQ + m * STRIDE + c4 * 4) = qv;
            *(float4*)(sK + m * STRIDE + c4 * 4) = kg[i];
            *(float4*)(sV + m * STRIDE + c4 * 4) = vg[i];
        }
    }
    __syncthreads();

    // ---- S = Q K^T (3-term tf32: near-fp32 accuracy) ------------------------
    float c[8][4];
#pragma unroll
    for (int n = 0; n < 8; ++n) { c[n][0] = 0.f; c[n][1] = 0.f; c[n][2] = 0.f; c[n][3] = 0.f; }

#pragma unroll
    for (int ks = 0; ks < 8; ++ks) {
        const int kc = ks * 8 + tig;
        float a0f = sQ[(r0 + g) * STRIDE + kc];
        float a1f = sQ[(r0 + g + 8) * STRIDE + kc];
        float a2f = sQ[(r0 + g) * STRIDE + kc + 4];
        float a3f = sQ[(r0 + g + 8) * STRIDE + kc + 4];
        uint32_t ah0, al0, ah1, al1, ah2, al2, ah3, al3;
        split_tf32(a0f, ah0, al0); split_tf32(a1f, ah1, al1);
        split_tf32(a2f, ah2, al2); split_tf32(a3f, ah3, al3);
#pragma unroll
        for (int n = 0; n < 8; ++n) {
            float b0f = sK[(n * 8 + g) * STRIDE + kc];
            float b1f = sK[(n * 8 + g) * STRIDE + kc + 4];
            uint32_t bh0, bl0, bh1, bl1;
            split_tf32(b0f, bh0, bl0);
            split_tf32(b1f, bh1, bl1);
            mma_tf32(c[n], ah0, ah1, ah2, ah3, bh0, bh1);
            mma_tf32(c[n], ah0, ah1, ah2, ah3, bl0, bl1);
            mma_tf32(c[n], al0, al1, al2, al3, bh0, bh1);
        }
    }

    // ---- add bias (precomputed, L2-resident) --------------------------------
    {
        const float* bp = g_bias + h * 4096;
#pragma unroll
        for (int n = 0; n < 8; ++n) {
            int col = n * 8 + 2 * tig;
            float2 b0 = *(const float2*)(bp + (r0 + g) * 64 + col);
            float2 b1 = *(const float2*)(bp + (r0 + g + 8) * 64 + col);
            c[n][0] += b0.x; c[n][1] += b0.y;
            c[n][2] += b1.x; c[n][3] += b1.y;
        }
    }

    // ---- softmax over m (row-wise; quad holds a full row) -------------------
    float mx0 = -1e30f, mx1 = -1e30f;
#pragma unroll
    for (int n = 0; n < 8; ++n) {
        mx0 = fmaxf(mx0, fmaxf(c[n][0], c[n][1]));
        mx1 = fmaxf(mx1, fmaxf(c[n][2], c[n][3]));
    }
    mx0 = fmaxf(mx0, __shfl_xor_sync(0xffffffffu, mx0, 1));
    mx0 = fmaxf(mx0, __shfl_xor_sync(0xffffffffu, mx0, 2));
    mx1 = fmaxf(mx1, __shfl_xor_sync(0xffffffffu, mx1, 1));
    mx1 = fmaxf(mx1, __shfl_xor_sync(0xffffffffu, mx1, 2));

    const float L2E = 1.4426950408889634f;
    float s0 = 0.f, s1 = 0.f;
#pragma unroll
    for (int n = 0; n < 8; ++n) {
        c[n][0] = exp2f((c[n][0] - mx0) * L2E);
        c[n][1] = exp2f((c[n][1] - mx0) * L2E);
        c[n][2] = exp2f((c[n][2] - mx1) * L2E);
        c[n][3] = exp2f((c[n][3] - mx1) * L2E);
        s0 += c[n][0] + c[n][1];
        s1 += c[n][2] + c[n][3];
    }
    s0 += __shfl_xor_sync(0xffffffffu, s0, 1);
    s0 += __shfl_xor_sync(0xffffffffu, s0, 2);
    s1 += __shfl_xor_sync(0xffffffffu, s1, 1);
    s1 += __shfl_xor_sync(0xffffffffu, s1, 2);
    float inv0 = 1.0f / s0;
    float inv1 = 1.0f / s1;

    // ---- stage unnormalized P in sQ (warp-private rows) ---------------------
#pragma unroll
    for (int n = 0; n < 8; ++n) {
        int col = n * 8 + 2 * tig;
        *(float2*)(sQ + (r0 + g) * STRIDE + col)     = make_float2(c[n][0], c[n][1]);
        *(float2*)(sQ + (r0 + g + 8) * STRIDE + col) = make_float2(c[n][2], c[n][3]);
    }
    __syncwarp();

    // ---- O = P V (P single tf32, V hi/lo split) -----------------------------
    float o[8][4];
#pragma unroll
    for (int d = 0; d < 8; ++d) { o[d][0] = 0.f; o[d][1] = 0.f; o[d][2] = 0.f; o[d][3] = 0.f; }

#pragma unroll
    for (int ks = 0; ks < 8; ++ks) {
        const int kc = ks * 8 + tig;
        uint32_t pa0 = f2tf32(sQ[(r0 + g) * STRIDE + kc]);
        uint32_t pa1 = f2tf32(sQ[(r0 + g + 8) * STRIDE + kc]);
        uint32_t pa2 = f2tf32(sQ[(r0 + g) * STRIDE + kc + 4]);
        uint32_t pa3 = f2tf32(sQ[(r0 + g + 8) * STRIDE + kc + 4]);
#pragma unroll
        for (int dt = 0; dt < 8; ++dt) {
            float b0f = sV[(ks * 8 + tig) * STRIDE + dt * 8 + g];
            float b1f = sV[(ks * 8 + tig + 4) * STRIDE + dt * 8 + g];
            uint32_t vh0, vl0, vh1, vl1;
            split_tf32(b0f, vh0, vl0);
            split_tf32(b1f, vh1, vl1);
            mma_tf32(o[dt], pa0, pa1, pa2, pa3, vh0, vh1);
            mma_tf32(o[dt], pa0, pa1, pa2, pa3, vl0, vl1);
        }
    }

    // ---- writeback with roll: out[b*32768 + n*512 + ((h*64+d-32)&511)] ------
    {
        float* ob = out + (size_t)b * 32768;
        const int cbase = h * 64 - 32;
        const int rowA = r0 + g, rowB = r0 + g + 8;
#pragma unroll
        for (int dt = 0; dt < 8; ++dt) {
            int d0 = dt * 8 + 2 * tig;
            int col = (cbase + d0) & 511;
            *(float2*)(ob + rowA * 512 + col) = make_float2(o[dt][0] * inv0, o[dt][1] * inv0);
            *(float2*)(ob + rowB * 512 + col) = make_float2(o[dt][2] * inv1, o[dt][3] * inv1);
        }
    }
}

extern "C" void kernel_launch(void* const* d_in, const int* in_sizes, int n_in,
                              void* d_out, int out_size) {
    const float* q     = (const float*)d_in[0];
    const float* k     = (const float*)d_in[1];
    const float* v     = (const float*)d_in[2];
    const float* table = (const float*)d_in[3];
    float* out = (float*)d_out;

    bias_precompute_kernel<<<16, 256>>>(table);

    const int smem_bytes = 3 * SM_TILE * sizeof(float);   // 52224 B
    cudaFuncSetAttribute(winattn_kernel,
                         cudaFuncAttributeMaxDynamicSharedMemorySize, smem_bytes);
    winattn_kernel<<<16384, 128, smem_bytes>>>(q, k, v, out);
}

// round 3
// speedup vs baseline: 1.2079x; 1.2079x over previous
#include <cuda_runtime.h>
#include <cstdint>

// ----------------------------------------------------------------------------
// WindowAttention: 2048 windows x 8 heads, M=N=64, D=64, fp32.
// One CTA per (b,h); 128 threads / 4 warps; warp w owns query rows [16w,16w+16).
// QK: Q split to tf32 hi/lo (exact), K single tf32 (pre-converted in smem).
// PV: P split to tf32 hi/lo (exact), V single tf32 (pre-converted in smem).
// Inner loops: 2xLDS + 2xHMMA only. Bias precomputed (x log2e). Rolled stores.
// ----------------------------------------------------------------------------

#define KSTRIDE 68                   // (mod 32 == 4): bank = 4g+tig, conflict-free
#define VSTRIDE 72                   // (mod 32 == 8): bank = 8tig+g, conflict-free
#define SK_FLOATS (64 * KSTRIDE)     // 4352 (also reused as P buffer)
#define SV_FLOATS (64 * VSTRIDE)     // 4608
#define SCALE_L2E 0.1803368801111146f // 0.125 * log2(e)

__device__ float g_bias[8 * 64 * 64];   // bias[h][n][m] * log2(e)

__global__ void bias_precompute_kernel(const float* __restrict__ table) {
    int t = blockIdx.x * blockDim.x + threadIdx.x;   // 0..4095 = n*64+m
    if (t >= 4096) return;
    int n = t >> 6, m = t & 63;
    int raw = (n - 32) * 128 + (m - 32) + 64;        // [-4064, 4063]
    int idx = raw < 0 ? raw + 16129 : raw;           // python-style mod
    const float* row = table + (size_t)idx * 8;
#pragma unroll
    for (int h = 0; h < 8; ++h)
        g_bias[h * 4096 + t] = row[h] * 1.4426950408889634f;
}

__device__ __forceinline__ uint32_t f2tf32(float x) {
    uint32_t r;
    asm("cvt.rna.tf32.f32 %0, %1;" : "=r"(r) : "f"(x));
    return r;
}

__device__ __forceinline__ void split_tf32(float x, uint32_t& hi, uint32_t& lo) {
    hi = f2tf32(x);
    lo = f2tf32(x - __uint_as_float(hi));
}

__device__ __forceinline__ void mma_tf32(float c[4],
                                         uint32_t a0, uint32_t a1, uint32_t a2, uint32_t a3,
                                         uint32_t b0, uint32_t b1) {
    asm volatile(
        "mma.sync.aligned.m16n8k8.row.col.f32.tf32.tf32.f32 "
        "{%0,%1,%2,%3}, {%4,%5,%6,%7}, {%8,%9}, {%0,%1,%2,%3};"
        : "+f"(c[0]), "+f"(c[1]), "+f"(c[2]), "+f"(c[3])
        : "r"(a0), "r"(a1), "r"(a2), "r"(a3), "r"(b0), "r"(b1));
}

__global__ __launch_bounds__(128) void winattn_kernel(
    const float* __restrict__ q, const float* __restrict__ k,
    const float* __restrict__ v, float* __restrict__ out) {
    extern __shared__ float smem[];
    float* sK = smem;                 // tf32-rounded K; reused as P buffer later
    float* sV = smem + SK_FLOATS;     // tf32-rounded V

    const int bh   = blockIdx.x;
    const int b    = bh >> 3;
    const int h    = bh & 7;
    const int tid  = threadIdx.x;
    const int lane = tid & 31;
    const int g    = lane >> 2;       // 0..7
    const int tig  = lane & 3;        // 0..3
    const int r0   = (tid >> 5) * 16; // warp's first query row

    // ---- stage K, V as tf32 bit patterns (one cvt per element, CTA-wide) ----
    {
        const float4* kg = (const float4*)(k + (size_t)bh * 4096);
        const float4* vg = (const float4*)(v + (size_t)bh * 4096);
#pragma unroll
        for (int i = tid; i < 1024; i += 128) {
            int m = i >> 4, c4 = i & 15;
            float4 kv = kg[i];
            float4 kt;
            kt.x = __uint_as_float(f2tf32(kv.x));
            kt.y = __uint_as_float(f2tf32(kv.y));
            kt.z = __uint_as_float(f2tf32(kv.z));
            kt.w = __uint_as_float(f2tf32(kv.w));
            *(float4*)(sK + m * KSTRIDE + c4 * 4) = kt;
            float4 vv = vg[i];
            float4 vt;
            vt.x = __uint_as_float(f2tf32(vv.x));
            vt.y = __uint_as_float(f2tf32(vv.y));
            vt.z = __uint_as_float(f2tf32(vv.z));
            vt.w = __uint_as_float(f2tf32(vv.w));
            *(float4*)(sV + m * VSTRIDE + c4 * 4) = vt;
        }
    }

    // ---- load this lane's 32 raw Q values straight to registers -------------
    float f0[8], f1[8], f2v[8], f3[8];
    {
        const float* qp = q + (size_t)bh * 4096 + (r0 + g) * 64 + tig;
#pragma unroll
        for (int ks = 0; ks < 8; ++ks) {
            f0[ks]  = qp[ks * 8];
            f2v[ks] = qp[ks * 8 + 4];
            f1[ks]  = qp[512 + ks * 8];       // row +8
            f3[ks]  = qp[512 + ks * 8 + 4];
        }
    }
    __syncthreads();

    // ---- S = Q K^T : Q exact (hi+lo), K single tf32 -------------------------
    float c[8][4];
#pragma unroll
    for (int n = 0; n < 8; ++n) { c[n][0] = 0.f; c[n][1] = 0.f; c[n][2] = 0.f; c[n][3] = 0.f; }

#pragma unroll
    for (int ks = 0; ks < 8; ++ks) {
        const int kc = ks * 8 + tig;
        uint32_t h0, l0, h1, l1, h2, l2, h3, l3;
        split_tf32(f0[ks], h0, l0); split_tf32(f1[ks], h1, l1);
        split_tf32(f2v[ks], h2, l2); split_tf32(f3[ks], h3, l3);
#pragma unroll
        for (int n = 0; n < 8; ++n) {
            uint32_t b0 = __float_as_uint(sK[(n * 8 + g) * KSTRIDE + kc]);
            uint32_t b1 = __float_as_uint(sK[(n * 8 + g) * KSTRIDE + kc + 4]);
            mma_tf32(c[n], h0, h1, h2, h3, b0, b1);
            mma_tf32(c[n], l0, l1, l2, l3, b0, b1);
        }
    }

    // ---- scale + bias (bias pre-multiplied by log2e) ------------------------
    {
        const float* bp = g_bias + h * 4096;
#pragma unroll
        for (int n = 0; n < 8; ++n) {
            int col = n * 8 + 2 * tig;
            float2 b0 = *(const float2*)(bp + (r0 + g) * 64 + col);
            float2 b1 = *(const float2*)(bp + (r0 + g + 8) * 64 + col);
            c[n][0] = fmaf(c[n][0], SCALE_L2E, b0.x);
            c[n][1] = fmaf(c[n][1], SCALE_L2E, b0.y);
            c[n][2] = fmaf(c[n][2], SCALE_L2E, b1.x);
            c[n][3] = fmaf(c[n][3], SCALE_L2E, b1.y);
        }
    }

    // ---- softmax (base-2 domain; quad holds a full row) ---------------------
    float mx0 = -1e30f, mx1 = -1e30f;
#pragma unroll
    for (int n = 0; n < 8; ++n) {
        mx0 = fmaxf(mx0, fmaxf(c[n][0], c[n][1]));
        mx1 = fmaxf(mx1, fmaxf(c[n][2], c[n][3]));
    }
    mx0 = fmaxf(mx0, __shfl_xor_sync(0xffffffffu, mx0, 1));
    mx0 = fmaxf(mx0, __shfl_xor_sync(0xffffffffu, mx0, 2));
    mx1 = fmaxf(mx1, __shfl_xor_sync(0xffffffffu, mx1, 1));
    mx1 = fmaxf(mx1, __shfl_xor_sync(0xffffffffu, mx1, 2));

    float s0 = 0.f, s1 = 0.f;
#pragma unroll
    for (int n = 0; n < 8; ++n) {
        c[n][0] = exp2f(c[n][0] - mx0);
        c[n][1] = exp2f(c[n][1] - mx0);
        c[n][2] = exp2f(c[n][2] - mx1);
        c[n][3] = exp2f(c[n][3] - mx1);
        s0 += c[n][0] + c[n][1];
        s1 += c[n][2] + c[n][3];
    }
    s0 += __shfl_xor_sync(0xffffffffu, s0, 1);
    s0 += __shfl_xor_sync(0xffffffffu, s0, 2);
    s1 += __shfl_xor_sync(0xffffffffu, s1, 1);
    s1 += __shfl_xor_sync(0xffffffffu, s1, 2);
    float inv0 = 1.0f / s0;
    float inv1 = 1.0f / s1;

    // ---- stage unnormalized P over sK (all warps done reading K) ------------
    __syncthreads();
    float* sP = sK;
#pragma unroll
    for (int n = 0; n < 8; ++n) {
        int col = n * 8 + 2 * tig;
        *(float2*)(sP + (r0 + g) * KSTRIDE + col)     = make_float2(c[n][0], c[n][1]);
        *(float2*)(sP + (r0 + g + 8) * KSTRIDE + col) = make_float2(c[n][2], c[n][3]);
    }
    __syncwarp();

    // ---- O = P V : P exact (hi+lo), V single tf32 ---------------------------
    float o[8][4];
#pragma unroll
    for (int d = 0; d < 8; ++d) { o[d][0] = 0.f; o[d][1] = 0.f; o[d][2] = 0.f; o[d][3] = 0.f; }

#pragma unroll
    for (int ks = 0; ks < 8; ++ks) {
        const int kc = ks * 8 + tig;
        uint32_t h0, l0, h1, l1, h2, l2, h3, l3;
        split_tf32(sP[(r0 + g) * KSTRIDE + kc],     h0, l0);
        split_tf32(sP[(r0 + g + 8) * KSTRIDE + kc], h1, l1);
        split_tf32(sP[(r0 + g) * KSTRIDE + kc + 4],     h2, l2);
        split_tf32(sP[(r0 + g + 8) * KSTRIDE + kc + 4], h3, l3);
#pragma unroll
        for (int dt = 0; dt < 8; ++dt) {
            uint32_t b0 = __float_as_uint(sV[(ks * 8 + tig) * VSTRIDE + dt * 8 + g]);
            uint32_t b1 = __float_as_uint(sV[(ks * 8 + tig + 4) * VSTRIDE + dt * 8 + g]);
            mma_tf32(o[dt], h0, h1, h2, h3, b0, b1);
            mma_tf32(o[dt], l0, l1, l2, l3, b0, b1);
        }
    }

    // ---- writeback with roll: out[b*32768 + n*512 + ((h*64+d-32)&511)] ------
    {
        float* ob = out + (size_t)b * 32768;
        const int cbase = h * 64 - 32;
        const int rowA = r0 + g, rowB = r0 + g + 8;
#pragma unroll
        for (int dt = 0; dt < 8; ++dt) {
            int d0 = dt * 8 + 2 * tig;
            int col = (cbase + d0) & 511;
            *(float2*)(ob + rowA * 512 + col) = make_float2(o[dt][0] * inv0, o[dt][1] * inv0);
            *(float2*)(ob + rowB * 512 + col) = make_float2(o[dt][2] * inv1, o[dt][3] * inv1);
        }
    }
}

extern "C" void kernel_launch(void* const* d_in, const int* in_sizes, int n_in,
                              void* d_out, int out_size) {
    const float* q     = (const float*)d_in[0];
    const float* k     = (const float*)d_in[1];
    const float* v     = (const float*)d_in[2];
    const float* table = (const float*)d_in[3];
    float* out = (float*)d_out;

    bias_precompute_kernel<<<16, 256>>>(table);

    const int smem_bytes = (SK_FLOATS + SV_FLOATS) * sizeof(float);   // 35840 B
    cudaFuncSetAttribute(winattn_kernel,
                         cudaFuncAttributeMaxDynamicSharedMemorySize, smem_bytes);
    winattn_kernel<<<16384, 128, smem_bytes>>>(q, k, v, out);
}

// round 4
// speedup vs baseline: 1.6606x; 1.3749x over previous
#include <cuda_runtime.h>
#include <cstdint>

// ----------------------------------------------------------------------------
// WindowAttention: 2048 windows x 8 heads, M=N=64, D=64, fp32.
// One CTA per (b,h); 128 threads / 4 warps; warp w owns query rows [16w,16w+16).
// QK: Q split tf32 hi/lo (exact), K single tf32. PV: P split, V single tf32.
// All global traffic coalesced: Q restaged via smem, bias pre-laid-out in
// fragment order, output staged via smem for row-contiguous float4 stores.
// ----------------------------------------------------------------------------

#define KSTRIDE 68                    // mod 32 == 4 -> bank 4g+tig, conflict-free
#define VSTRIDE 72                    // mod 32 == 8 -> bank 8tig+g, conflict-free
#define SK_FLOATS (64 * KSTRIDE)      // 4352 (Q stage -> K tile -> P -> O stage)
#define SV_FLOATS (64 * VSTRIDE)      // 4608
#define SCALE_L2E 0.1803368801111146f // 0.125 * log2(e)

// bias in fragment order: [h][w][n][lane] float4 =
//   { b[rA][8n+2tig], b[rA][8n+2tig+1], b[rB][8n+2tig], b[rB][8n+2tig+1] } * log2e
// rA = 16w + (lane>>2), rB = rA + 8, tig = lane&3.  8*4*8*32 float4 = 128 KB.
__device__ float4 g_biasF[8 * 4 * 8 * 32];

__global__ void bias_precompute_kernel(const float* __restrict__ table) {
    int t = blockIdx.x * blockDim.x + threadIdx.x;   // 0..8191
    if (t >= 8192) return;
    int h = t >> 10, w = (t >> 8) & 3, n = (t >> 5) & 7, lane = t & 31;
    int g = lane >> 2, tig = lane & 3;
    int rA = 16 * w + g, rB = rA + 8;
    int col = 8 * n + 2 * tig;
    const float L2E = 1.4426950408889634f;
    float4 r;
#define BIAS_AT(rr, cc, dst) {                                   \
        int raw = ((rr) - 32) * 128 + ((cc) - 32) + 64;          \
        int idx = raw < 0 ? raw + 16129 : raw;                   \
        dst = table[(size_t)idx * 8 + h] * L2E; }
    BIAS_AT(rA, col,     r.x);
    BIAS_AT(rA, col + 1, r.y);
    BIAS_AT(rB, col,     r.z);
    BIAS_AT(rB, col + 1, r.w);
#undef BIAS_AT
    g_biasF[t] = r;
}

__device__ __forceinline__ uint32_t f2tf32(float x) {
    uint32_t r;
    asm("cvt.rna.tf32.f32 %0, %1;" : "=r"(r) : "f"(x));
    return r;
}

__device__ __forceinline__ void split_tf32(float x, uint32_t& hi, uint32_t& lo) {
    hi = f2tf32(x);
    lo = f2tf32(x - __uint_as_float(hi));
}

__device__ __forceinline__ void mma_tf32(float c[4],
                                         uint32_t a0, uint32_t a1, uint32_t a2, uint32_t a3,
                                         uint32_t b0, uint32_t b1) {
    asm volatile(
        "mma.sync.aligned.m16n8k8.row.col.f32.tf32.tf32.f32 "
        "{%0,%1,%2,%3}, {%4,%5,%6,%7}, {%8,%9}, {%0,%1,%2,%3};"
        : "+f"(c[0]), "+f"(c[1]), "+f"(c[2]), "+f"(c[3])
        : "r"(a0), "r"(a1), "r"(a2), "r"(a3), "r"(b0), "r"(b1));
}

__global__ __launch_bounds__(128) void winattn_kernel(
    const float* __restrict__ q, const float* __restrict__ k,
    const float* __restrict__ v, float* __restrict__ out) {
    extern __shared__ float smem[];
    float* sK = smem;                 // Q stage -> tf32 K -> P -> O stage
    float* sV = smem + SK_FLOATS;     // tf32 V

    const int bh   = blockIdx.x;
    const int b    = bh >> 3;
    const int h    = bh & 7;
    const int tid  = threadIdx.x;
    const int lane = tid & 31;
    const int g    = lane >> 2;       // 0..7
    const int tig  = lane & 3;        // 0..3
    const int w    = tid >> 5;
    const int r0   = w * 16;          // warp's first query row

    // ---- phase A: coalesced Q -> smem (borrow sK region) --------------------
    {
        const float4* qg = (const float4*)(q + (size_t)bh * 4096);
#pragma unroll
        for (int i = tid; i < 1024; i += 128) {
            int m = i >> 4, c4 = i & 15;
            *(float4*)(sK + m * KSTRIDE + c4 * 4) = qg[i];
        }
    }
    __syncthreads();

    // ---- phase B: this lane's 32 raw Q values -> registers ------------------
    float f0[8], f1[8], f2v[8], f3[8];
    {
        const float* qA = sK + (r0 + g) * KSTRIDE + tig;
        const float* qB = sK + (r0 + g + 8) * KSTRIDE + tig;
#pragma unroll
        for (int ks = 0; ks < 8; ++ks) {
            f0[ks]  = qA[ks * 8];
            f2v[ks] = qA[ks * 8 + 4];
            f1[ks]  = qB[ks * 8];
            f3[ks]  = qB[ks * 8 + 4];
        }
    }
    __syncthreads();

    // ---- phase C: stage K, V as tf32 bit patterns (coalesced) ---------------
    {
        const float4* kg = (const float4*)(k + (size_t)bh * 4096);
        const float4* vg = (const float4*)(v + (size_t)bh * 4096);
#pragma unroll
        for (int i = tid; i < 1024; i += 128) {
            int m = i >> 4, c4 = i & 15;
            float4 kv = kg[i];
            float4 kt;
            kt.x = __uint_as_float(f2tf32(kv.x));
            kt.y = __uint_as_float(f2tf32(kv.y));
            kt.z = __uint_as_float(f2tf32(kv.z));
            kt.w = __uint_as_float(f2tf32(kv.w));
            *(float4*)(sK + m * KSTRIDE + c4 * 4) = kt;
            float4 vv = vg[i];
            float4 vt;
            vt.x = __uint_as_float(f2tf32(vv.x));
            vt.y = __uint_as_float(f2tf32(vv.y));
            vt.z = __uint_as_float(f2tf32(vv.z));
            vt.w = __uint_as_float(f2tf32(vv.w));
            *(float4*)(sV + m * VSTRIDE + c4 * 4) = vt;
        }
    }
    __syncthreads();

    // ---- S = Q K^T : Q exact (hi+lo), K single tf32 -------------------------
    float c[8][4];
#pragma unroll
    for (int n = 0; n < 8; ++n) { c[n][0] = 0.f; c[n][1] = 0.f; c[n][2] = 0.f; c[n][3] = 0.f; }

#pragma unroll
    for (int ks = 0; ks < 8; ++ks) {
        const int kc = ks * 8 + tig;
        uint32_t h0, l0, h1, l1, h2, l2, h3, l3;
        split_tf32(f0[ks], h0, l0); split_tf32(f1[ks], h1, l1);
        split_tf32(f2v[ks], h2, l2); split_tf32(f3[ks], h3, l3);
#pragma unroll
        for (int n = 0; n < 8; ++n) {
            uint32_t b0 = __float_as_uint(sK[(n * 8 + g) * KSTRIDE + kc]);
            uint32_t b1 = __float_as_uint(sK[(n * 8 + g) * KSTRIDE + kc + 4]);
            mma_tf32(c[n], h0, h1, h2, h3, b0, b1);
            mma_tf32(c[n], l0, l1, l2, l3, b0, b1);
        }
    }

    // ---- scale + bias (fragment-order, coalesced LDG.128, L2-resident) ------
    {
        const float4* bf = g_biasF + ((h * 4 + w) * 8) * 32 + lane;
#pragma unroll
        for (int n = 0; n < 8; ++n) {
            float4 bb = bf[n * 32];
            c[n][0] = fmaf(c[n][0], SCALE_L2E, bb.x);
            c[n][1] = fmaf(c[n][1], SCALE_L2E, bb.y);
            c[n][2] = fmaf(c[n][2], SCALE_L2E, bb.z);
            c[n][3] = fmaf(c[n][3], SCALE_L2E, bb.w);
        }
    }

    // ---- softmax (base-2 domain; quad holds a full row) ---------------------
    float mx0 = -1e30f, mx1 = -1e30f;
#pragma unroll
    for (int n = 0; n < 8; ++n) {
        mx0 = fmaxf(mx0, fmaxf(c[n][0], c[n][1]));
        mx1 = fmaxf(mx1, fmaxf(c[n][2], c[n][3]));
    }
    mx0 = fmaxf(mx0, __shfl_xor_sync(0xffffffffu, mx0, 1));
    mx0 = fmaxf(mx0, __shfl_xor_sync(0xffffffffu, mx0, 2));
    mx1 = fmaxf(mx1, __shfl_xor_sync(0xffffffffu, mx1, 1));
    mx1 = fmaxf(mx1, __shfl_xor_sync(0xffffffffu, mx1, 2));

    float s0 = 0.f, s1 = 0.f;
#pragma unroll
    for (int n = 0; n < 8; ++n) {
        c[n][0] = exp2f(c[n][0] - mx0);
        c[n][1] = exp2f(c[n][1] - mx0);
        c[n][2] = exp2f(c[n][2] - mx1);
        c[n][3] = exp2f(c[n][3] - mx1);
        s0 += c[n][0] + c[n][1];
        s1 += c[n][2] + c[n][3];
    }
    s0 += __shfl_xor_sync(0xffffffffu, s0, 1);
    s0 += __shfl_xor_sync(0xffffffffu, s0, 2);
    s1 += __shfl_xor_sync(0xffffffffu, s1, 1);
    s1 += __shfl_xor_sync(0xffffffffu, s1, 2);
    float inv0 = 1.0f / s0;
    float inv1 = 1.0f / s1;

    // ---- stage unnormalized P over sK (all warps done reading K) ------------
    __syncthreads();
    float* sP = sK;
#pragma unroll
    for (int n = 0; n < 8; ++n) {
        int col = n * 8 + 2 * tig;
        *(float2*)(sP + (r0 + g) * KSTRIDE + col)     = make_float2(c[n][0], c[n][1]);
        *(float2*)(sP + (r0 + g + 8) * KSTRIDE + col) = make_float2(c[n][2], c[n][3]);
    }
    __syncwarp();

    // ---- O = P V : P exact (hi+lo), V single tf32 ---------------------------
    float o[8][4];
#pragma unroll
    for (int d = 0; d < 8; ++d) { o[d][0] = 0.f; o[d][1] = 0.f; o[d][2] = 0.f; o[d][3] = 0.f; }

#pragma unroll
    for (int ks = 0; ks < 8; ++ks) {
        const int kc = ks * 8 + tig;
        uint32_t h0, l0, h1, l1, h2, l2, h3, l3;
        split_tf32(sP[(r0 + g) * KSTRIDE + kc],         h0, l0);
        split_tf32(sP[(r0 + g + 8) * KSTRIDE + kc],     h1, l1);
        split_tf32(sP[(r0 + g) * KSTRIDE + kc + 4],     h2, l2);
        split_tf32(sP[(r0 + g + 8) * KSTRIDE + kc + 4], h3, l3);
#pragma unroll
        for (int dt = 0; dt < 8; ++dt) {
            uint32_t b0 = __float_as_uint(sV[(ks * 8 + tig) * VSTRIDE + dt * 8 + g]);
            uint32_t b1 = __float_as_uint(sV[(ks * 8 + tig + 4) * VSTRIDE + dt * 8 + g]);
            mma_tf32(o[dt], h0, h1, h2, h3, b0, b1);
            mma_tf32(o[dt], l0, l1, l2, l3, b0, b1);
        }
    }

    // ---- stage normalized O in smem (reuse sP region), then coalesced STG ---
    __syncthreads();          // everyone done reading sP
    float* sO = sK;
#pragma unroll
    for (int dt = 0; dt < 8; ++dt) {
        int col = dt * 8 + 2 * tig;
        *(float2*)(sO + (r0 + g) * KSTRIDE + col)     = make_float2(o[dt][0] * inv0, o[dt][1] * inv0);
        *(float2*)(sO + (r0 + g + 8) * KSTRIDE + col) = make_float2(o[dt][2] * inv1, o[dt][3] * inv1);
    }
    __syncthreads();

    // out[b*32768 + row*512 + ((h*64 + d - 32) & 511)], row-contiguous float4
    {
        float* ob = out + (size_t)b * 32768;
        const int cbase = h * 64 - 32;
        const int c4 = tid & 15;            // 16 float4 per row
        const int col = (cbase + 4 * c4) & 511;
#pragma unroll
        for (int it = 0; it < 8; ++it) {
            int row = (tid >> 4) + 8 * it;
            float4 val = *(const float4*)(sO + row * KSTRIDE + c4 * 4);
            *(float4*)(ob + row * 512 + col) = val;
        }
    }
}

extern "C" void kernel_launch(void* const* d_in, const int* in_sizes, int n_in,
                              void* d_out, int out_size) {
    const float* q     = (const float*)d_in[0];
    const float* k     = (const float*)d_in[1];
    const float* v     = (const float*)d_in[2];
    const float* table = (const float*)d_in[3];
    float* out = (float*)d_out;

    bias_precompute_kernel<<<32, 256>>>(table);

    const int smem_bytes = (SK_FLOATS + SV_FLOATS) * sizeof(float);   // 35840 B
    cudaFuncSetAttribute(winattn_kernel,
                         cudaFuncAttributeMaxDynamicSharedMemorySize, smem_bytes);
    winattn_kernel<<<16384, 128, smem_bytes>>>(q, k, v, out);
}

// round 5
// speedup vs baseline: 1.6608x; 1.0001x over previous
#include <cuda_runtime.h>
#include <cstdint>

// ----------------------------------------------------------------------------
// WindowAttention: 2048 windows x 8 heads, M=N=64, D=64, fp32.
// One CTA per (b,h); 128 threads / 4 warps; warp w owns query rows [16w,16w+16).
// QK: Q split tf32 hi/lo (exact), K single tf32. PV: P split, V single tf32.
// All global traffic coalesced: Q restaged via smem, bias pre-laid-out in
// fragment order, output staged via smem for row-contiguous float4 stores.
// ----------------------------------------------------------------------------

#define KSTRIDE 68                    // mod 32 == 4 -> bank 4g+tig, conflict-free
#define VSTRIDE 72                    // mod 32 == 8 -> bank 8tig+g, conflict-free
#define SK_FLOATS (64 * KSTRIDE)      // 4352 (Q stage -> K tile -> P -> O stage)
#define SV_FLOATS (64 * VSTRIDE)      // 4608
#define SCALE_L2E 0.1803368801111146f // 0.125 * log2(e)

// bias in fragment order: [h][w][n][lane] float4 =
//   { b[rA][8n+2tig], b[rA][8n+2tig+1], b[rB][8n+2tig], b[rB][8n+2tig+1] } * log2e
// rA = 16w + (lane>>2), rB = rA + 8, tig = lane&3.  8*4*8*32 float4 = 128 KB.
__device__ float4 g_biasF[8 * 4 * 8 * 32];

__global__ void bias_precompute_kernel(const float* __restrict__ table) {
    int t = blockIdx.x * blockDim.x + threadIdx.x;   // 0..8191
    if (t >= 8192) return;
    int h = t >> 10, w = (t >> 8) & 3, n = (t >> 5) & 7, lane = t & 31;
    int g = lane >> 2, tig = lane & 3;
    int rA = 16 * w + g, rB = rA + 8;
    int col = 8 * n + 2 * tig;
    const float L2E = 1.4426950408889634f;
    float4 r;
#define BIAS_AT(rr, cc, dst) {                                   \
        int raw = ((rr) - 32) * 128 + ((cc) - 32) + 64;          \
        int idx = raw < 0 ? raw + 16129 : raw;                   \
        dst = table[(size_t)idx * 8 + h] * L2E; }
    BIAS_AT(rA, col,     r.x);
    BIAS_AT(rA, col + 1, r.y);
    BIAS_AT(rB, col,     r.z);
    BIAS_AT(rB, col + 1, r.w);
#undef BIAS_AT
    g_biasF[t] = r;
}

__device__ __forceinline__ uint32_t f2tf32(float x) {
    uint32_t r;
    asm("cvt.rna.tf32.f32 %0, %1;" : "=r"(r) : "f"(x));
    return r;
}

__device__ __forceinline__ void split_tf32(float x, uint32_t& hi, uint32_t& lo) {
    hi = f2tf32(x);
    lo = f2tf32(x - __uint_as_float(hi));
}

__device__ __forceinline__ void mma_tf32(float c[4],
                                         uint32_t a0, uint32_t a1, uint32_t a2, uint32_t a3,
                                         uint32_t b0, uint32_t b1) {
    asm volatile(
        "mma.sync.aligned.m16n8k8.row.col.f32.tf32.tf32.f32 "
        "{%0,%1,%2,%3}, {%4,%5,%6,%7}, {%8,%9}, {%0,%1,%2,%3};"
        : "+f"(c[0]), "+f"(c[1]), "+f"(c[2]), "+f"(c[3])
        : "r"(a0), "r"(a1), "r"(a2), "r"(a3), "r"(b0), "r"(b1));
}

__global__ __launch_bounds__(128) void winattn_kernel(
    const float* __restrict__ q, const float* __restrict__ k,
    const float* __restrict__ v, float* __restrict__ out) {
    extern __shared__ float smem[];
    float* sK = smem;                 // Q stage -> tf32 K -> P -> O stage
    float* sV = smem + SK_FLOATS;     // tf32 V

    const int bh   = blockIdx.x;
    const int b    = bh >> 3;
    const int h    = bh & 7;
    const int tid  = threadIdx.x;
    const int lane = tid & 31;
    const int g    = lane >> 2;       // 0..7
    const int tig  = lane & 3;        // 0..3
    const int w    = tid >> 5;
    const int r0   = w * 16;          // warp's first query row

    // ---- phase A: coalesced Q -> smem (borrow sK region) --------------------
    {
        const float4* qg = (const float4*)(q + (size_t)bh * 4096);
#pragma unroll
        for (int i = tid; i < 1024; i += 128) {
            int m = i >> 4, c4 = i & 15;
            *(float4*)(sK + m * KSTRIDE + c4 * 4) = qg[i];
        }
    }
    __syncthreads();

    // ---- phase B: this lane's 32 raw Q values -> registers ------------------
    float f0[8], f1[8], f2v[8], f3[8];
    {
        const float* qA = sK + (r0 + g) * KSTRIDE + tig;
        const float* qB = sK + (r0 + g + 8) * KSTRIDE + tig;
#pragma unroll
        for (int ks = 0; ks < 8; ++ks) {
            f0[ks]  = qA[ks * 8];
            f2v[ks] = qA[ks * 8 + 4];
            f1[ks]  = qB[ks * 8];
            f3[ks]  = qB[ks * 8 + 4];
        }
    }
    __syncthreads();

    // ---- phase C: stage K, V as tf32 bit patterns (coalesced) ---------------
    {
        const float4* kg = (const float4*)(k + (size_t)bh * 4096);
        const float4* vg = (const float4*)(v + (size_t)bh * 4096);
#pragma unroll
        for (int i = tid; i < 1024; i += 128) {
            int m = i >> 4, c4 = i & 15;
            float4 kv = kg[i];
            float4 kt;
            kt.x = __uint_as_float(f2tf32(kv.x));
            kt.y = __uint_as_float(f2tf32(kv.y));
            kt.z = __uint_as_float(f2tf32(kv.z));
            kt.w = __uint_as_float(f2tf32(kv.w));
            *(float4*)(sK + m * KSTRIDE + c4 * 4) = kt;
            float4 vv = vg[i];
            float4 vt;
            vt.x = __uint_as_float(f2tf32(vv.x));
            vt.y = __uint_as_float(f2tf32(vv.y));
            vt.z = __uint_as_float(f2tf32(vv.z));
            vt.w = __uint_as_float(f2tf32(vv.w));
            *(float4*)(sV + m * VSTRIDE + c4 * 4) = vt;
        }
    }
    __syncthreads();

    // ---- S = Q K^T : Q exact (hi+lo), K single tf32 -------------------------
    float c[8][4];
#pragma unroll
    for (int n = 0; n < 8; ++n) { c[n][0] = 0.f; c[n][1] = 0.f; c[n][2] = 0.f; c[n][3] = 0.f; }

#pragma unroll
    for (int ks = 0; ks < 8; ++ks) {
        const int kc = ks * 8 + tig;
        uint32_t h0, l0, h1, l1, h2, l2, h3, l3;
        split_tf32(f0[ks], h0, l0); split_tf32(f1[ks], h1, l1);
        split_tf32(f2v[ks], h2, l2); split_tf32(f3[ks], h3, l3);
#pragma unroll
        for (int n = 0; n < 8; ++n) {
            uint32_t b0 = __float_as_uint(sK[(n * 8 + g) * KSTRIDE + kc]);
            uint32_t b1 = __float_as_uint(sK[(n * 8 + g) * KSTRIDE + kc + 4]);
            mma_tf32(c[n], h0, h1, h2, h3, b0, b1);
            mma_tf32(c[n], l0, l1, l2, l3, b0, b1);
        }
    }

    // ---- scale + bias (fragment-order, coalesced LDG.128, L2-resident) ------
    {
        const float4* bf = g_biasF + ((h * 4 + w) * 8) * 32 + lane;
#pragma unroll
        for (int n = 0; n < 8; ++n) {
            float4 bb = bf[n * 32];
            c[n][0] = fmaf(c[n][0], SCALE_L2E, bb.x);
            c[n][1] = fmaf(c[n][1], SCALE_L2E, bb.y);
            c[n][2] = fmaf(c[n][2], SCALE_L2E, bb.z);
            c[n][3] = fmaf(c[n][3], SCALE_L2E, bb.w);
        }
    }

    // ---- softmax (base-2 domain; quad holds a full row) ---------------------
    float mx0 = -1e30f, mx1 = -1e30f;
#pragma unroll
    for (int n = 0; n < 8; ++n) {
        mx0 = fmaxf(mx0, fmaxf(c[n][0], c[n][1]));
        mx1 = fmaxf(mx1, fmaxf(c[n][2], c[n][3]));
    }
    mx0 = fmaxf(mx0, __shfl_xor_sync(0xffffffffu, mx0, 1));
    mx0 = fmaxf(mx0, __shfl_xor_sync(0xffffffffu, mx0, 2));
    mx1 = fmaxf(mx1, __shfl_xor_sync(0xffffffffu, mx1, 1));
    mx1 = fmaxf(mx1, __shfl_xor_sync(0xffffffffu, mx1, 2));

    float s0 = 0.f, s1 = 0.f;
#pragma unroll
    for (int n = 0; n < 8; ++n) {
        c[n][0] = exp2f(c[n][0] - mx0);
        c[n][1] = exp2f(c[n][1] - mx0);
        c[n][2] = exp2f(c[n][2] - mx1);
        c[n][3] = exp2f(c[n][3] - mx1);
        s0 += c[n][0] + c[n][1];
        s1 += c[n][2] + c[n][3];
    }
    s0 += __shfl_xor_sync(0xffffffffu, s0, 1);
    s0 += __shfl_xor_sync(0xffffffffu, s0, 2);
    s1 += __shfl_xor_sync(0xffffffffu, s1, 1);
    s1 += __shfl_xor_sync(0xffffffffu, s1, 2);
    float inv0 = 1.0f / s0;
    float inv1 = 1.0f / s1;

    // ---- stage unnormalized P over sK (all warps done reading K) ------------
    __syncthreads();
    float* sP = sK;
#pragma unroll
    for (int n = 0; n < 8; ++n) {
        int col = n * 8 + 2 * tig;
        *(float2*)(sP + (r0 + g) * KSTRIDE + col)     = make_float2(c[n][0], c[n][1]);
        *(float2*)(sP + (r0 + g + 8) * KSTRIDE + col) = make_float2(c[n][2], c[n][3]);
    }
    __syncwarp();

    // ---- O = P V : P exact (hi+lo), V single tf32 ---------------------------
    float o[8][4];
#pragma unroll
    for (int d = 0; d < 8; ++d) { o[d][0] = 0.f; o[d][1] = 0.f; o[d][2] = 0.f; o[d][3] = 0.f; }

#pragma unroll
    for (int ks = 0; ks < 8; ++ks) {
        const int kc = ks * 8 + tig;
        uint32_t h0, l0, h1, l1, h2, l2, h3, l3;
        split_tf32(sP[(r0 + g) * KSTRIDE + kc],         h0, l0);
        split_tf32(sP[(r0 + g + 8) * KSTRIDE + kc],     h1, l1);
        split_tf32(sP[(r0 + g) * KSTRIDE + kc + 4],     h2, l2);
        split_tf32(sP[(r0 + g + 8) * KSTRIDE + kc + 4], h3, l3);
#pragma unroll
        for (int dt = 0; dt < 8; ++dt) {
            uint32_t b0 = __float_as_uint(sV[(ks * 8 + tig) * VSTRIDE + dt * 8 + g]);
            uint32_t b1 = __float_as_uint(sV[(ks * 8 + tig + 4) * VSTRIDE + dt * 8 + g]);
            mma_tf32(o[dt], h0, h1, h2, h3, b0, b1);
            mma_tf32(o[dt], l0, l1, l2, l3, b0, b1);
        }
    }

    // ---- stage normalized O in smem (reuse sP region), then coalesced STG ---
    __syncthreads();          // everyone done reading sP
    float* sO = sK;
#pragma unroll
    for (int dt = 0; dt < 8; ++dt) {
        int col = dt * 8 + 2 * tig;
        *(float2*)(sO + (r0 + g) * KSTRIDE + col)     = make_float2(o[dt][0] * inv0, o[dt][1] * inv0);
        *(float2*)(sO + (r0 + g + 8) * KSTRIDE + col) = make_float2(o[dt][2] * inv1, o[dt][3] * inv1);
    }
    __syncthreads();

    // out[b*32768 + row*512 + ((h*64 + d - 32) & 511)], row-contiguous float4
    {
        float* ob = out + (size_t)b * 32768;
        const int cbase = h * 64 - 32;
        const int c4 = tid & 15;            // 16 float4 per row
        const int col = (cbase + 4 * c4) & 511;
#pragma unroll
        for (int it = 0; it < 8; ++it) {
            int row = (tid >> 4) + 8 * it;
            float4 val = *(const float4*)(sO + row * KSTRIDE + c4 * 4);
            *(float4*)(ob + row * 512 + col) = val;
        }
    }
}

extern "C" void kernel_launch(void* const* d_in, const int* in_sizes, int n_in,
                              void* d_out, int out_size) {
    const float* q     = (const float*)d_in[0];
    const float* k     = (const float*)d_in[1];
    const float* v     = (const float*)d_in[2];
    const float* table = (const float*)d_in[3];
    float* out = (float*)d_out;

    bias_precompute_kernel<<<32, 256>>>(table);

    const int smem_bytes = (SK_FLOATS + SV_FLOATS) * sizeof(float);   // 35840 B
    cudaFuncSetAttribute(winattn_kernel,
                         cudaFuncAttributeMaxDynamicSharedMemorySize, smem_bytes);
    winattn_kernel<<<16384, 128, smem_bytes>>>(q, k, v, out);
}